// round 2
// baseline (speedup 1.0000x reference)
#include <cuda_runtime.h>
#include <cstdint>

// Residual quantizer, fp32, mirroring the JAX/XLA-CPU reference arithmetic:
//   distances = (sum(r^2) - 2*(r @ cb.T)) + sum(cb^2)        [exact association]
//   dot accumulated sequentially over the 64 dims with FMA   [Eigen gebp order]
//   sums-of-squares as square-then-add, sequential
//   quantized = ((q0+q1)+q2)+q3 ;  quantized_st = z + (quantized - z)
//
// Math engine: packed fma.rn.f32x2 with the TWO LANES spanning two CODES
// (not two dims), so each lane's accumulation is a pure sequential-in-dim
// FMA chain — bitwise-reproducible vs a sequential CPU microkernel — while
// retaining 2 MACs/instruction. Codebook is staged transposed [dim][code]
// in SMEM (row stride 260 floats: 16B-aligned rows, conflict-free stores),
// loaded with uniform-address ld.shared.v2.u64 broadcasts.

#define KCODES 256
#define DIM 64
#define LEVELS 4
#define ROWS 260                               // padded floats per dim-row
#define ROWB (ROWS * 4)                        // 1040 bytes, 16B aligned
#define SMEM_BYTES (DIM * ROWB + KCODES * 4)   // 66560 + 1024 = 67584

#define FMA2(d, a, b, c) \
    asm("fma.rn.f32x2 %0, %1, %2, %3;" : "=l"(d) : "l"(a), "l"(b), "l"(c))

__global__ void __launch_bounds__(256, 2)
rq_kernel(const float* __restrict__ z, const float* __restrict__ cb,
          float* __restrict__ out, int B) {
    extern __shared__ __align__(16) float smem[];
    float* c2 = smem + DIM * ROWS;

    const int p_raw = blockIdx.x * 256 + threadIdx.x;
    const int p = p_raw < B ? p_raw : (B - 1);     // clamp; writes gated below
    const int tid = threadIdx.x;

    // ---- load z into 64 scalar residual registers ----
    float r[DIM];
    const float4* zp = reinterpret_cast<const float4*>(z + (size_t)p * DIM);
#pragma unroll
    for (int i = 0; i < 16; i++) {
        float4 v = zp[i];
        r[4 * i + 0] = v.x; r[4 * i + 1] = v.y;
        r[4 * i + 2] = v.z; r[4 * i + 3] = v.w;
    }

    const unsigned sm0 = (unsigned)__cvta_generic_to_shared(smem);
    int idxs[LEVELS];

#pragma unroll 1
    for (int lvl = 0; lvl < LEVELS; lvl++) {
        __syncthreads();
        // ---- transpose-load codebook level: smem[j*ROWS + k] = cb[lvl][k][j]
        // thread k owns code row k: contiguous global reads, conflict-free STS
        {
            const float4* src = reinterpret_cast<const float4*>(
                cb + ((size_t)lvl * KCODES + tid) * DIM);
#pragma unroll
            for (int i = 0; i < 16; i++) {
                float4 v = src[i];
                smem[(4 * i + 0) * ROWS + tid] = v.x;
                smem[(4 * i + 1) * ROWS + tid] = v.y;
                smem[(4 * i + 2) * ROWS + tid] = v.z;
                smem[(4 * i + 3) * ROWS + tid] = v.w;
            }
        }
        __syncthreads();
        // ---- c2[k] = sum(cb[k]**2): square-then-add, sequential over dims
        {
            float s = 0.f;
#pragma unroll
            for (int j = 0; j < DIM; j++) {
                float c = smem[j * ROWS + tid];
                s = __fadd_rn(s, __fmul_rn(c, c));
            }
            c2[tid] = s;
        }
        __syncthreads();

        // ---- r2 = sum(residual**2): square-then-add, sequential
        float r2 = 0.f;
#pragma unroll
        for (int j = 0; j < DIM; j++)
            r2 = __fadd_rn(r2, __fmul_rn(r[j], r[j]));

        // ---- argmin over 256 codes, 8 codes (4 lane-pairs) per group ----
        float best = __int_as_float(0x7F800000);   // +inf
        int bi = 0;
#pragma unroll 1
        for (int kp = 0; kp < KCODES / 2; kp += 4) {
            unsigned long long a0 = 0ULL, a1 = 0ULL, a2 = 0ULL, a3 = 0ULL;
            unsigned base = sm0 + kp * 8;
#pragma unroll
            for (int j = 0; j < DIM; j++) {
                unsigned long long rb;
                asm("mov.b64 %0, {%1, %1};" : "=l"(rb) : "f"(r[j]));
                unsigned long long cA, cB, cC, cD;
                unsigned ad = base + j * ROWB;     // 16B aligned (ROWB=1040)
                asm("ld.shared.v2.u64 {%0,%1}, [%2];"
                    : "=l"(cA), "=l"(cB) : "r"(ad));
                asm("ld.shared.v2.u64 {%0,%1}, [%2];"
                    : "=l"(cC), "=l"(cD) : "r"(ad + 16));
                FMA2(a0, rb, cA, a0);
                FMA2(a1, rb, cB, a1);
                FMA2(a2, rb, cC, a2);
                FMA2(a3, rb, cD, a3);
            }
            unsigned long long accs[4] = {a0, a1, a2, a3};
#pragma unroll
            for (int u = 0; u < 4; u++) {
                float lo, hi;
                asm("mov.b64 {%0,%1}, %2;" : "=f"(lo), "=f"(hi) : "l"(accs[u]));
                int k0 = 2 * (kp + u);
                // dist = (r2 - 2*dot) + c2   -- reference association, rn ops
                float d0 = __fadd_rn(__fsub_rn(r2, __fmul_rn(2.0f, lo)), c2[k0]);
                float d1 = __fadd_rn(__fsub_rn(r2, __fmul_rn(2.0f, hi)), c2[k0 + 1]);
                if (d0 < best) { best = d0; bi = k0; }
                if (d1 < best) { best = d1; bi = k0 + 1; }
            }
        }
        idxs[lvl] = bi;

        // ---- residual -= chosen code (round-exact mirror of ref) ----
#pragma unroll
        for (int j = 0; j < DIM; j++)
            r[j] = __fsub_rn(r[j], smem[j * ROWS + bi]);
    }

    if (p_raw >= B) return;

    // ---- quantized = ((q0 + q1) + q2) + q3, sequential level adds ----
    float q[DIM];
#pragma unroll
    for (int j = 0; j < DIM; j++) q[j] = 0.f;
#pragma unroll 1
    for (int lvl = 0; lvl < LEVELS; lvl++) {
        const float4* cp = reinterpret_cast<const float4*>(
            cb + ((size_t)lvl * KCODES + idxs[lvl]) * DIM);
#pragma unroll
        for (int i = 0; i < 16; i++) {
            float4 v = cp[i];
            q[4 * i + 0] = __fadd_rn(q[4 * i + 0], v.x);
            q[4 * i + 1] = __fadd_rn(q[4 * i + 1], v.y);
            q[4 * i + 2] = __fadd_rn(q[4 * i + 2], v.z);
            q[4 * i + 3] = __fadd_rn(q[4 * i + 3], v.w);
        }
    }

    // ---- outputs: [quantized_st | indices(f32) | quantized] ----
    float4* qst = reinterpret_cast<float4*>(out + (size_t)p * DIM);
    float4* qq  = reinterpret_cast<float4*>(out + (size_t)B * (DIM + 4) +
                                            (size_t)p * DIM);
#pragma unroll
    for (int i = 0; i < 16; i++) {
        float4 zv = zp[i];
        float4 qv = make_float4(q[4 * i + 0], q[4 * i + 1],
                                q[4 * i + 2], q[4 * i + 3]);
        // quantized_st = z + (quantized - z)
        float4 sv;
        sv.x = __fadd_rn(zv.x, __fsub_rn(qv.x, zv.x));
        sv.y = __fadd_rn(zv.y, __fsub_rn(qv.y, zv.y));
        sv.z = __fadd_rn(zv.z, __fsub_rn(qv.z, zv.z));
        sv.w = __fadd_rn(zv.w, __fsub_rn(qv.w, zv.w));
        qst[i] = sv;
        qq[i] = qv;
    }
    float4 iv;
    iv.x = (float)idxs[0];
    iv.y = (float)idxs[1];
    iv.z = (float)idxs[2];
    iv.w = (float)idxs[3];
    reinterpret_cast<float4*>(out + (size_t)B * DIM)[p] = iv;
}

extern "C" void kernel_launch(void* const* d_in, const int* in_sizes, int n_in,
                              void* d_out, int out_size) {
    const float* z = (const float*)d_in[0];
    const float* cb = (const float*)d_in[1];
    float* out = (float*)d_out;
    int B = in_sizes[0] / DIM;

    cudaFuncSetAttribute(rq_kernel, cudaFuncAttributeMaxDynamicSharedMemorySize,
                         SMEM_BYTES);
    int blocks = (B + 255) / 256;
    rq_kernel<<<blocks, 256, SMEM_BYTES>>>(z, cb, out, B);
}